// round 16
// baseline (speedup 1.0000x reference)
#include <cuda_runtime.h>
#include <cuda_fp16.h>
#include <cstdint>

// Problem constants
#define Bb   8
#define Cc   256
#define Nn   2048
#define Kk   16
#define OUTd 256
#define KD   512                 // 2*C
#define BN_TOT (Bb*Nn)           // 16384
#define NT2  256                 // N tiles of 64
#define MTILES 2                 // 256/128

// ---- scratch (static device globals; no dynamic allocation) ----
__device__ __half g_xsH[BN_TOT * Cc];   // fp16 node-major features
__device__ float g_si [BN_TOT];
__device__ float g_sj [BN_TOT];
__device__ int   g_is64;

// int8 split operands (Q = qh*128 + ql, |Q| <= 16256), row-major [rows][512]
__device__ signed char g_FQh[(size_t)BN_TOT * KD];
__device__ signed char g_FQl[(size_t)BN_TOT * KD];
__device__ signed char g_WQh[(size_t)OUTd * KD];
__device__ signed char g_WQl[(size_t)OUTd * KD];
__device__ float g_sf[BN_TOT];          // per-feature-row scale
__device__ float g_sa[OUTd];            // per-weight-row scale

// ============================================================
// helpers
// ============================================================
__device__ __forceinline__ uint32_t smem_u32(const void* p) {
    uint32_t a;
    asm("{ .reg .u64 t; cvta.to.shared.u64 t, %1; cvt.u32.u64 %0, t; }"
        : "=r"(a) : "l"(p));
    return a;
}
__device__ __forceinline__ void ldm4(uint32_t* r, uint32_t addr) {
    asm volatile("ldmatrix.sync.aligned.m8n8.x4.shared.b16 {%0,%1,%2,%3}, [%4];"
                 : "=r"(r[0]), "=r"(r[1]), "=r"(r[2]), "=r"(r[3]) : "r"(addr));
}
__device__ __forceinline__ void imma(int* d, const uint32_t* a, const uint32_t* b) {
    asm volatile(
        "mma.sync.aligned.m16n8k32.row.col.s32.s8.s8.s32 "
        "{%0,%1,%2,%3}, {%4,%5,%6,%7}, {%8,%9}, {%0,%1,%2,%3};"
        : "+r"(d[0]), "+r"(d[1]), "+r"(d[2]), "+r"(d[3])
        : "r"(a[0]), "r"(a[1]), "r"(a[2]), "r"(a[3]), "r"(b[0]), "r"(b[1]));
}
#define CP16(dst, src) asm volatile("cp.async.cg.shared.global [%0], [%1], 16;" :: "r"(dst), "l"(src))
#define CP_COMMIT()    asm volatile("cp.async.commit_group;" ::: "memory")
#define CP_WAIT1()     asm volatile("cp.async.wait_group 1;" ::: "memory")
#define CP_WAIT0()     asm volatile("cp.async.wait_group 0;" ::: "memory")

__device__ __forceinline__ void quant2(float v, float inv, signed char& qh,
                                       signed char& ql) {
    int Q = __float2int_rn(v * inv);         // |Q| <= 16256
    int h = (Q + 64) >> 7;                   // round(Q/128)
    qh = (signed char)h;
    ql = (signed char)(Q - (h << 7));        // in [-64,64]
}

// swizzled byte offset of 16B chunk c in row r (pitch 64):
//   r*64 + (c ^ ((r>>1)&3))*16  -> ldmatrix conflict-free for
//   8-row groups starting at r % 8 == 0, any fixed c.
__device__ __forceinline__ uint32_t sws(int r, int c) {
    return (uint32_t)(r * 64 + ((c ^ ((r >> 1) & 3)) << 4));
}

// ============================================================
// K0: weight int8 hi/lo quantization (one block = one row) +
//     edge-dtype detection in block 0.
// ============================================================
__global__ void k_wq(const float* __restrict__ W, const int* __restrict__ e) {
    const int lane = threadIdx.x;            // 32 threads
    if (blockIdx.x == 0) {
        int bad = 0;
        #pragma unroll
        for (int i = lane; i < 256; i += 32) bad |= e[2 * i + 1];
        #pragma unroll
        for (int o = 16; o; o >>= 1) bad |= __shfl_xor_sync(0xffffffffu, bad, o);
        if (!lane) g_is64 = (bad == 0) ? 1 : 0;
    }
    const int row = blockIdx.x;
    const float* wp = W + (size_t)row * KD + lane * 16;
    float vals[16];
    float mx = 0.f;
    #pragma unroll
    for (int j = 0; j < 16; j++) { vals[j] = wp[j]; mx = fmaxf(mx, fabsf(vals[j])); }
    #pragma unroll
    for (int o = 16; o; o >>= 1) mx = fmaxf(mx, __shfl_xor_sync(0xffffffffu, mx, o));
    const float M   = fmaxf(mx, 1e-20f);
    const float inv = 16256.f / M;
    union { uint4 u; signed char c[16]; } H, L;
    #pragma unroll
    for (int j = 0; j < 16; j++) quant2(vals[j], inv, H.c[j], L.c[j]);
    const size_t o = (size_t)row * KD + lane * 16;
    *(uint4*)(g_WQh + o) = H.u;
    *(uint4*)(g_WQl + o) = L.u;
    if (!lane) g_sa[row] = M * (1.f / 16256.f);
}

// ============================================================
// K1: FUSED transpose + attention pre-scores.
// ============================================================
__global__ __launch_bounds__(256) void k_transpose(const float* __restrict__ x,
                                                   const float* __restrict__ aw) {
    __shared__ float tile[32][33];
    __shared__ float sred[8][32][2];
    const int b   = blockIdx.y;
    const int n0  = blockIdx.x * 32;
    const int tx  = threadIdx.x;             // 0..31
    const int ty  = threadIdx.y;             // 0..7
    const int tid = ty * 32 + tx;
    const float* xb = x + (size_t)b * Cc * Nn;
    __half* xt = g_xsH + (size_t)b * Nn * Cc;

    float ai = 0.f, aj = 0.f;                // score partials for node n0+tx
    #pragma unroll 1
    for (int c0 = 0; c0 < Cc; c0 += 32) {
        __syncthreads();                     // tile reuse guard
        #pragma unroll
        for (int i = 0; i < 32; i += 8) {
            const int c = c0 + ty + i;
            const float v = xb[(size_t)c * Nn + n0 + tx];
            tile[ty + i][tx] = v;
            ai += v * __ldg(aw + c);
            aj += v * __ldg(aw + Cc + c);
        }
        __syncthreads();
        #pragma unroll
        for (int i = 0; i < 32; i += 8)
            xt[(size_t)(n0 + ty + i) * Cc + c0 + tx] =
                __float2half_rn(tile[tx][ty + i]);
    }
    sred[ty][tx][0] = ai;
    sred[ty][tx][1] = aj;
    __syncthreads();
    if (tid < 64) {
        const int node  = tid & 31;
        const int which = tid >> 5;
        float s = 0.f;
        #pragma unroll
        for (int r = 0; r < 8; r++) s += sred[r][node][which];
        if (which) g_sj[b * Nn + n0 + node] = s;
        else       g_si[b * Nn + n0 + node] = s;
    }
}

// ============================================================
// K4: warp-per-node FUSED softmax + aggregation + int8 quant.
// ============================================================
__global__ __launch_bounds__(256) void k_agg(const int* __restrict__ edge,
                                             const float* __restrict__ ab) {
    const int warp = threadIdx.x >> 5;
    const int lane = threadIdx.x & 31;
    const int bn   = blockIdx.x * 8 + warp;
    const int b    = bn >> 11;

    // --- softmax: lanes 0..15 and 16..31 compute identical halves ---
    const int sh  = g_is64;
    const int k16 = lane & 15;
    const size_t ei = (size_t)(bn * Kk + k16) << sh;
    const int i0 = edge[ei] & (Nn - 1);
    const int i1 = edge[(((size_t)BN_TOT * Kk) << sh) + ei] & (Nn - 1);
    const float e = g_si[b * Nn + i1] + g_sj[b * Nn + i0] + ab[0];
    float m = e;
    #pragma unroll
    for (int o = 8; o; o >>= 1) m = fmaxf(m, __shfl_xor_sync(0xffffffffu, m, o));
    const float ev = expf(e - m);
    float s = ev;
    #pragma unroll
    for (int o = 8; o; o >>= 1) s += __shfl_xor_sync(0xffffffffu, s, o);
    const float w  = ev / s;
    const int joff = i0 * 32;                // row offset in uint4 units

    // --- aggregation: uint4 gathers (8 halfs/lane), fp32 accum ---
    const uint4* base4 = (const uint4*)(g_xsH + (size_t)b * Nn * Cc);
    const uint4 craw = base4[(bn & (Nn - 1)) * 32 + lane];   // center, 8 halfs
    float a0 = 0.f, a1 = 0.f, a2 = 0.f, a3 = 0.f;
    float a4 = 0.f, a5 = 0.f, a6 = 0.f, a7 = 0.f;
    #pragma unroll
    for (int k = 0; k < Kk; k++) {
        const float wk = __shfl_sync(0xffffffffu, w, k);
        const int   jo = __shfl_sync(0xffffffffu, joff, k);
        const uint4 raw = base4[jo + lane];
        const float2 p0 = __half22float2(*(const __half2*)&raw.x);
        const float2 p1 = __half22float2(*(const __half2*)&raw.y);
        const float2 p2 = __half22float2(*(const __half2*)&raw.z);
        const float2 p3 = __half22float2(*(const __half2*)&raw.w);
        a0 += wk * p0.x; a1 += wk * p0.y; a2 += wk * p1.x; a3 += wk * p1.y;
        a4 += wk * p2.x; a5 += wk * p2.y; a6 += wk * p3.x; a7 += wk * p3.y;
    }
    const float2 c0 = __half22float2(*(const __half2*)&craw.x);
    const float2 c1 = __half22float2(*(const __half2*)&craw.y);
    const float2 c2 = __half22float2(*(const __half2*)&craw.z);
    const float2 c3 = __half22float2(*(const __half2*)&craw.w);
    const float v[16] = {c0.x, a0, c0.y, a1, c1.x, a2, c1.y, a3,
                         c2.x, a4, c2.y, a5, c3.x, a6, c3.y, a7};

    float mx = 0.f;
    #pragma unroll
    for (int j = 0; j < 16; j++) mx = fmaxf(mx, fabsf(v[j]));
    #pragma unroll
    for (int o = 16; o; o >>= 1) mx = fmaxf(mx, __shfl_xor_sync(0xffffffffu, mx, o));
    const float M   = fmaxf(mx, 1e-20f);
    const float inv = 16256.f / M;
    union { uint4 u; signed char ch[16]; } H, L;
    #pragma unroll
    for (int j = 0; j < 16; j++) quant2(v[j], inv, H.ch[j], L.ch[j]);
    const size_t o = (size_t)bn * KD + 16 * lane;
    *(uint4*)(g_FQh + o) = H.u;
    *(uint4*)(g_FQl + o) = L.u;
    if (!lane) g_sf[bn] = M * (1.f / 16256.f);
}

// ============================================================
// K5: int8-split GEMM, CTA 128(M)x64(N), BK=64 per stage,
//     2 CTAs/SM, 8 warps, 32x32 warp tiles, cp.async x2 buffers.
//     Warp-staggered sub-chunk order to break post-barrier
//     ldmatrix/IMMA convoys; accm hl/lh writes separated.
// ============================================================
#define SROWS  384
#define BUFB   (SROWS * 64)       // 24576 bytes per buffer

__global__ __launch_bounds__(256, 2)
void k_gemm_i8(const float* __restrict__ bias, float* __restrict__ out) {
    __shared__ __align__(16) signed char sm[2][SROWS][64];

    const int tid  = threadIdx.x;
    const int lane = tid & 31;
    const int warp = tid >> 5;
    const int wm   = warp >> 1;     // 0..3  (m offset wm*32)
    const int wn   = warp & 1;      // 0..1  (n offset wn*32)
    const int nt   = blockIdx.x;    // 0..255 (64-col tiles)
    const int mt   = blockIdx.y;    // 0..1
    const uint32_t smb = smem_u32(sm);

    // staging: W rows via (tid>>1, 2 chunks), F rows via (tid>>2, 1 chunk)
    const int rowW = tid >> 1;              // 0..127
    const int chW  = (tid & 1) * 2;         // chunks {0,1} or {2,3}
    const int rowF = tid >> 2;              // 0..63
    const int chF  = tid & 3;               // 0..3
    const signed char* pWH = g_WQh + (size_t)(mt * 128 + rowW) * KD + chW * 16;
    const signed char* pWL = g_WQl + (size_t)(mt * 128 + rowW) * KD + chW * 16;
    const signed char* pFH = g_FQh + (size_t)(nt * 64 + rowF) * KD + chF * 16;
    const signed char* pFL = g_FQl + (size_t)(nt * 64 + rowF) * KD + chF * 16;
    const uint32_t dWH0 = smb + sws(rowW, chW);
    const uint32_t dWH1 = smb + sws(rowW, chW + 1);
    const uint32_t dWL0 = smb + sws(128 + rowW, chW);
    const uint32_t dWL1 = smb + sws(128 + rowW, chW + 1);
    const uint32_t dFH  = smb + sws(256 + rowF, chF);
    const uint32_t dFL  = smb + sws(320 + rowF, chF);

    // prologue: stages 0 and 1 in flight (stage = 64 bytes of K)
    #pragma unroll
    for (int s = 0; s < 2; s++) {
        const int ko = s * 64;
        const uint32_t bo = s * BUFB;
        CP16(dWH0 + bo, pWH + ko);
        CP16(dWH1 + bo, pWH + ko + 16);
        CP16(dWL0 + bo, pWL + ko);
        CP16(dWL1 + bo, pWL + ko + 16);
        CP16(dFH + bo, pFH + ko);
        CP16(dFL + bo, pFL + ko);
        CP_COMMIT();
    }

    int acch[2][4][4], accm[2][4][4];
    #pragma unroll
    for (int i = 0; i < 2; i++)
        #pragma unroll
        for (int j = 0; j < 4; j++)
            #pragma unroll
            for (int q = 0; q < 4; q++) { acch[i][j][q] = 0; accm[i][j][q] = 0; }

    const int arow = wm * 32 + (lane & 7) + ((lane >> 3) & 1) * 8;   // + mf*16
    const int ach  = (lane >> 4) & 1;                                // chunk within K=32
    const int brow = wn * 32 + ((lane >> 4) & 1) * 8 + (lane & 7);   // + p*16
    const int bch  = (lane >> 3) & 1;
    const int ks0  = warp & 1;          // stagger: sub-chunk start parity
    const int mf0  = (warp >> 1) & 1;   // stagger: mf start parity

    #pragma unroll 1
    for (int kt = 0; kt < KD / 64; kt++) {       // 8 stages
        const int buf = kt & 1;
        if (kt < KD / 64 - 1) CP_WAIT1(); else CP_WAIT0();
        __syncthreads();
        const uint32_t sb = smb + buf * BUFB;

        #pragma unroll
        for (int ksi = 0; ksi < 2; ksi++) {      // warp-staggered order
            const int ks = ksi ^ ks0;
            const int cA = ks * 2 + ach;
            const int cB = ks * 2 + bch;
            uint32_t bqh[4][2], bql[4][2];
            #pragma unroll
            for (int p = 0; p < 2; p++) {
                uint32_t r[4];
                ldm4(r, sb + sws(256 + brow + p * 16, cB));
                bqh[2 * p][0] = r[0]; bqh[2 * p][1] = r[1];
                bqh[2 * p + 1][0] = r[2]; bqh[2 * p + 1][1] = r[3];
                ldm4(r, sb + sws(320 + brow + p * 16, cB));
                bql[2 * p][0] = r[0]; bql[2 * p][1] = r[1];
                bql[2 * p + 1][0] = r[2]; bql[2 * p + 1][1] = r[3];
            }
            #pragma unroll
            for (int mfi = 0; mfi < 2; mfi++) {
                const int mf = mfi ^ mf0;
                uint32_t ah[4], al[4];
                ldm4(ah, sb + sws(arow + mf * 16, cA));
                ldm4(al, sb + sws(128 + arow + mf * 16, cA));
                // hh + hl sweep, then lh sweep: the two writes to each
                // accm are >=4 instructions apart (breaks RAW chain).
                #pragma unroll
                for (int nf = 0; nf < 4; nf++) {
                    imma(acch[mf][nf], ah, bqh[nf]);   // hh
                    imma(accm[mf][nf], ah, bql[nf]);   // hl
                }
                #pragma unroll
                for (int nf = 0; nf < 4; nf++)
                    imma(accm[mf][nf], al, bqh[nf]);   // lh
            }
        }
        __syncthreads();
        if (kt + 2 < KD / 64) {
            const int ko = (kt + 2) * 64;
            const uint32_t bo = buf * BUFB;
            CP16(dWH0 + bo, pWH + ko);
            CP16(dWH1 + bo, pWH + ko + 16);
            CP16(dWL0 + bo, pWL + ko);
            CP16(dWL1 + bo, pWL + ko + 16);
            CP16(dFH + bo, pFH + ko);
            CP16(dFL + bo, pFL + ko);
            CP_COMMIT();
        }
    }

    // epilogue: scale-combine + bias + relu
    const int g    = lane >> 2;
    const int tig  = lane & 3;
    const int bidx = nt >> 5;                  // 32 tiles per batch
    float sbv[4][2];
    #pragma unroll
    for (int nf = 0; nf < 4; nf++) {
        const int col = nt * 64 + wn * 32 + 2 * tig + nf * 8;
        sbv[nf][0] = g_sf[col];
        sbv[nf][1] = g_sf[col + 1];
    }
    const int nb0 = (nt & 31) * 64 + wn * 32 + 2 * tig;
    #pragma unroll
    for (int mf = 0; mf < 2; mf++) {
        const int o0 = mt * 128 + wm * 32 + mf * 16 + g;
        const float sa0 = g_sa[o0], sa1 = g_sa[o0 + 8];
        const float b0  = bias[o0], b1  = bias[o0 + 8];
        float* r0 = out + ((size_t)(bidx * OUTd + o0) * Nn);
        float* r1 = out + ((size_t)(bidx * OUTd + o0 + 8) * Nn);
        #pragma unroll
        for (int nf = 0; nf < 4; nf++) {
            const int nb = nb0 + nf * 8;
            const float t0 = 16384.f * (float)acch[mf][nf][0] + 128.f * (float)accm[mf][nf][0];
            const float t1 = 16384.f * (float)acch[mf][nf][1] + 128.f * (float)accm[mf][nf][1];
            const float t2 = 16384.f * (float)acch[mf][nf][2] + 128.f * (float)accm[mf][nf][2];
            const float t3 = 16384.f * (float)acch[mf][nf][3] + 128.f * (float)accm[mf][nf][3];
            float2 w0, w1;
            w0.x = fmaxf(fmaf(t0, sa0 * sbv[nf][0], b0), 0.f);
            w0.y = fmaxf(fmaf(t1, sa0 * sbv[nf][1], b0), 0.f);
            w1.x = fmaxf(fmaf(t2, sa1 * sbv[nf][0], b1), 0.f);
            w1.y = fmaxf(fmaf(t3, sa1 * sbv[nf][1], b1), 0.f);
            *(float2*)(r0 + nb) = w0;
            *(float2*)(r1 + nb) = w1;
        }
    }
}

// ============================================================
// launch
// ============================================================
extern "C" void kernel_launch(void* const* d_in, const int* in_sizes, int n_in,
                              void* d_out, int out_size) {
    const float* x    = (const float*)d_in[0];
    const int*   edge = (const int*)d_in[1];
    const float* a_w  = (const float*)d_in[2];
    const float* a_b  = (const float*)d_in[3];
    const float* nn_w = (const float*)d_in[4];
    const float* nn_b = (const float*)d_in[5];
    float*       out  = (float*)d_out;

    k_wq       <<<OUTd, 32>>>(nn_w, edge);
    k_transpose<<<dim3(Nn / 32, Bb), dim3(32, 8)>>>(x, a_w);
    k_agg      <<<BN_TOT / 8, 256>>>(edge, a_b);
    k_gemm_i8  <<<dim3(NT2, MTILES), 256>>>(nn_b, out);
}

// round 17
// speedup vs baseline: 2.1957x; 2.1957x over previous
#include <cuda_runtime.h>
#include <cuda_fp16.h>
#include <cstdint>

// Problem constants
#define Bb   8
#define Cc   256
#define Nn   2048
#define Kk   16
#define OUTd 256
#define KD   512                 // 2*C
#define BN_TOT (Bb*Nn)           // 16384
#define NT2  256                 // N tiles of 64
#define MTILES 2                 // 256/128

// ---- scratch (static device globals; no dynamic allocation) ----
__device__ __half g_xsH[BN_TOT * Cc];   // fp16 node-major features
__device__ float g_si [BN_TOT];
__device__ float g_sj [BN_TOT];
__device__ int   g_is64;

// int8 split operands (Q = qh*128 + ql, |Q| <= 16256), row-major [rows][512]
__device__ signed char g_FQh[(size_t)BN_TOT * KD];
__device__ signed char g_FQl[(size_t)BN_TOT * KD];
__device__ signed char g_WQh[(size_t)OUTd * KD];
__device__ signed char g_WQl[(size_t)OUTd * KD];
__device__ float g_sf[BN_TOT];          // per-feature-row scale
__device__ float g_sa[OUTd];            // per-weight-row scale

// ============================================================
// helpers
// ============================================================
__device__ __forceinline__ uint32_t smem_u32(const void* p) {
    uint32_t a;
    asm("{ .reg .u64 t; cvta.to.shared.u64 t, %1; cvt.u32.u64 %0, t; }"
        : "=r"(a) : "l"(p));
    return a;
}
__device__ __forceinline__ void ldm4(uint32_t* r, uint32_t addr) {
    asm volatile("ldmatrix.sync.aligned.m8n8.x4.shared.b16 {%0,%1,%2,%3}, [%4];"
                 : "=r"(r[0]), "=r"(r[1]), "=r"(r[2]), "=r"(r[3]) : "r"(addr));
}
__device__ __forceinline__ void imma(int* d, const uint32_t* a, const uint32_t* b) {
    asm volatile(
        "mma.sync.aligned.m16n8k32.row.col.s32.s8.s8.s32 "
        "{%0,%1,%2,%3}, {%4,%5,%6,%7}, {%8,%9}, {%0,%1,%2,%3};"
        : "+r"(d[0]), "+r"(d[1]), "+r"(d[2]), "+r"(d[3])
        : "r"(a[0]), "r"(a[1]), "r"(a[2]), "r"(a[3]), "r"(b[0]), "r"(b[1]));
}
#define CP16(dst, src) asm volatile("cp.async.cg.shared.global [%0], [%1], 16;" :: "r"(dst), "l"(src))
#define CP_COMMIT()    asm volatile("cp.async.commit_group;" ::: "memory")
#define CP_WAIT1()     asm volatile("cp.async.wait_group 1;" ::: "memory")
#define CP_WAIT0()     asm volatile("cp.async.wait_group 0;" ::: "memory")

__device__ __forceinline__ void quant2(float v, float inv, signed char& qh,
                                       signed char& ql) {
    int Q = __float2int_rn(v * inv);         // |Q| <= 16256
    int h = (Q + 64) >> 7;                   // round(Q/128)
    qh = (signed char)h;
    ql = (signed char)(Q - (h << 7));        // in [-64,64]
}

// swizzled byte offset of 16B chunk c in row r (pitch 64):
//   r*64 + (c ^ ((r>>1)&3))*16  -> ldmatrix conflict-free for
//   8-row groups starting at r % 8 == 0, any fixed c.
__device__ __forceinline__ uint32_t sws(int r, int c) {
    return (uint32_t)(r * 64 + ((c ^ ((r >> 1) & 3)) << 4));
}

// ============================================================
// K0: weight int8 hi/lo quantization (one block = one row) +
//     edge-dtype detection in block 0.
// ============================================================
__global__ void k_wq(const float* __restrict__ W, const int* __restrict__ e) {
    const int lane = threadIdx.x;            // 32 threads
    if (blockIdx.x == 0) {
        int bad = 0;
        #pragma unroll
        for (int i = lane; i < 256; i += 32) bad |= e[2 * i + 1];
        #pragma unroll
        for (int o = 16; o; o >>= 1) bad |= __shfl_xor_sync(0xffffffffu, bad, o);
        if (!lane) g_is64 = (bad == 0) ? 1 : 0;
    }
    const int row = blockIdx.x;
    const float* wp = W + (size_t)row * KD + lane * 16;
    float vals[16];
    float mx = 0.f;
    #pragma unroll
    for (int j = 0; j < 16; j++) { vals[j] = wp[j]; mx = fmaxf(mx, fabsf(vals[j])); }
    #pragma unroll
    for (int o = 16; o; o >>= 1) mx = fmaxf(mx, __shfl_xor_sync(0xffffffffu, mx, o));
    const float M   = fmaxf(mx, 1e-20f);
    const float inv = 16256.f / M;
    union { uint4 u; signed char c[16]; } H, L;
    #pragma unroll
    for (int j = 0; j < 16; j++) quant2(vals[j], inv, H.c[j], L.c[j]);
    const size_t o = (size_t)row * KD + lane * 16;
    *(uint4*)(g_WQh + o) = H.u;
    *(uint4*)(g_WQl + o) = L.u;
    if (!lane) g_sa[row] = M * (1.f / 16256.f);
}

// ============================================================
// K1: FUSED transpose + attention pre-scores.
// ============================================================
__global__ __launch_bounds__(256) void k_transpose(const float* __restrict__ x,
                                                   const float* __restrict__ aw) {
    __shared__ float tile[32][33];
    __shared__ float sred[8][32][2];
    const int b   = blockIdx.y;
    const int n0  = blockIdx.x * 32;
    const int tx  = threadIdx.x;             // 0..31
    const int ty  = threadIdx.y;             // 0..7
    const int tid = ty * 32 + tx;
    const float* xb = x + (size_t)b * Cc * Nn;
    __half* xt = g_xsH + (size_t)b * Nn * Cc;

    float ai = 0.f, aj = 0.f;                // score partials for node n0+tx
    #pragma unroll 1
    for (int c0 = 0; c0 < Cc; c0 += 32) {
        __syncthreads();                     // tile reuse guard
        #pragma unroll
        for (int i = 0; i < 32; i += 8) {
            const int c = c0 + ty + i;
            const float v = xb[(size_t)c * Nn + n0 + tx];
            tile[ty + i][tx] = v;
            ai += v * __ldg(aw + c);
            aj += v * __ldg(aw + Cc + c);
        }
        __syncthreads();
        #pragma unroll
        for (int i = 0; i < 32; i += 8)
            xt[(size_t)(n0 + ty + i) * Cc + c0 + tx] =
                __float2half_rn(tile[tx][ty + i]);
    }
    sred[ty][tx][0] = ai;
    sred[ty][tx][1] = aj;
    __syncthreads();
    if (tid < 64) {
        const int node  = tid & 31;
        const int which = tid >> 5;
        float s = 0.f;
        #pragma unroll
        for (int r = 0; r < 8; r++) s += sred[r][node][which];
        if (which) g_sj[b * Nn + n0 + node] = s;
        else       g_si[b * Nn + n0 + node] = s;
    }
}

// ============================================================
// K4: warp-per-node FUSED softmax + aggregation + int8 quant.
// ============================================================
__global__ __launch_bounds__(256) void k_agg(const int* __restrict__ edge,
                                             const float* __restrict__ ab) {
    const int warp = threadIdx.x >> 5;
    const int lane = threadIdx.x & 31;
    const int bn   = blockIdx.x * 8 + warp;
    const int b    = bn >> 11;

    // --- softmax: lanes 0..15 and 16..31 compute identical halves ---
    const int sh  = g_is64;
    const int k16 = lane & 15;
    const size_t ei = (size_t)(bn * Kk + k16) << sh;
    const int i0 = edge[ei] & (Nn - 1);
    const int i1 = edge[(((size_t)BN_TOT * Kk) << sh) + ei] & (Nn - 1);
    const float e = g_si[b * Nn + i1] + g_sj[b * Nn + i0] + ab[0];
    float m = e;
    #pragma unroll
    for (int o = 8; o; o >>= 1) m = fmaxf(m, __shfl_xor_sync(0xffffffffu, m, o));
    const float ev = expf(e - m);
    float s = ev;
    #pragma unroll
    for (int o = 8; o; o >>= 1) s += __shfl_xor_sync(0xffffffffu, s, o);
    const float w  = ev / s;
    const int joff = i0 * 32;                // row offset in uint4 units

    // --- aggregation: uint4 gathers (8 halfs/lane), fp32 accum ---
    const uint4* base4 = (const uint4*)(g_xsH + (size_t)b * Nn * Cc);
    const uint4 craw = base4[(bn & (Nn - 1)) * 32 + lane];   // center, 8 halfs
    float a0 = 0.f, a1 = 0.f, a2 = 0.f, a3 = 0.f;
    float a4 = 0.f, a5 = 0.f, a6 = 0.f, a7 = 0.f;
    #pragma unroll
    for (int k = 0; k < Kk; k++) {
        const float wk = __shfl_sync(0xffffffffu, w, k);
        const int   jo = __shfl_sync(0xffffffffu, joff, k);
        const uint4 raw = base4[jo + lane];
        const float2 p0 = __half22float2(*(const __half2*)&raw.x);
        const float2 p1 = __half22float2(*(const __half2*)&raw.y);
        const float2 p2 = __half22float2(*(const __half2*)&raw.z);
        const float2 p3 = __half22float2(*(const __half2*)&raw.w);
        a0 += wk * p0.x; a1 += wk * p0.y; a2 += wk * p1.x; a3 += wk * p1.y;
        a4 += wk * p2.x; a5 += wk * p2.y; a6 += wk * p3.x; a7 += wk * p3.y;
    }
    const float2 c0 = __half22float2(*(const __half2*)&craw.x);
    const float2 c1 = __half22float2(*(const __half2*)&craw.y);
    const float2 c2 = __half22float2(*(const __half2*)&craw.z);
    const float2 c3 = __half22float2(*(const __half2*)&craw.w);
    const float v[16] = {c0.x, a0, c0.y, a1, c1.x, a2, c1.y, a3,
                         c2.x, a4, c2.y, a5, c3.x, a6, c3.y, a7};

    float mx = 0.f;
    #pragma unroll
    for (int j = 0; j < 16; j++) mx = fmaxf(mx, fabsf(v[j]));
    #pragma unroll
    for (int o = 16; o; o >>= 1) mx = fmaxf(mx, __shfl_xor_sync(0xffffffffu, mx, o));
    const float M   = fmaxf(mx, 1e-20f);
    const float inv = 16256.f / M;
    union { uint4 u; signed char ch[16]; } H, L;
    #pragma unroll
    for (int j = 0; j < 16; j++) quant2(v[j], inv, H.ch[j], L.ch[j]);
    const size_t o = (size_t)bn * KD + 16 * lane;
    *(uint4*)(g_FQh + o) = H.u;
    *(uint4*)(g_FQl + o) = L.u;
    if (!lane) g_sf[bn] = M * (1.f / 16256.f);
}

// ============================================================
// K5: int8-split GEMM, CTA 128(M)x64(N), BK=64 per stage,
//     2 CTAs/SM, 8 warps, 32x32 warp tiles, cp.async x2 buffers.
//     R15 structure (compile-time loop order) + RAW-split IMMA
//     ordering: per mf, hh+hl sweep then lh sweep.
// ============================================================
#define SROWS  384
#define BUFB   (SROWS * 64)       // 24576 bytes per buffer

__global__ __launch_bounds__(256, 2)
void k_gemm_i8(const float* __restrict__ bias, float* __restrict__ out) {
    __shared__ __align__(16) signed char sm[2][SROWS][64];

    const int tid  = threadIdx.x;
    const int lane = tid & 31;
    const int warp = tid >> 5;
    const int wm   = warp >> 1;     // 0..3  (m offset wm*32)
    const int wn   = warp & 1;      // 0..1  (n offset wn*32)
    const int nt   = blockIdx.x;    // 0..255 (64-col tiles)
    const int mt   = blockIdx.y;    // 0..1
    const uint32_t smb = smem_u32(sm);

    // staging: W rows via (tid>>1, 2 chunks), F rows via (tid>>2, 1 chunk)
    const int rowW = tid >> 1;              // 0..127
    const int chW  = (tid & 1) * 2;         // chunks {0,1} or {2,3}
    const int rowF = tid >> 2;              // 0..63
    const int chF  = tid & 3;               // 0..3
    const signed char* pWH = g_WQh + (size_t)(mt * 128 + rowW) * KD + chW * 16;
    const signed char* pWL = g_WQl + (size_t)(mt * 128 + rowW) * KD + chW * 16;
    const signed char* pFH = g_FQh + (size_t)(nt * 64 + rowF) * KD + chF * 16;
    const signed char* pFL = g_FQl + (size_t)(nt * 64 + rowF) * KD + chF * 16;
    const uint32_t dWH0 = smb + sws(rowW, chW);
    const uint32_t dWH1 = smb + sws(rowW, chW + 1);
    const uint32_t dWL0 = smb + sws(128 + rowW, chW);
    const uint32_t dWL1 = smb + sws(128 + rowW, chW + 1);
    const uint32_t dFH  = smb + sws(256 + rowF, chF);
    const uint32_t dFL  = smb + sws(320 + rowF, chF);

    // prologue: stages 0 and 1 in flight (stage = 64 bytes of K)
    #pragma unroll
    for (int s = 0; s < 2; s++) {
        const int ko = s * 64;
        const uint32_t bo = s * BUFB;
        CP16(dWH0 + bo, pWH + ko);
        CP16(dWH1 + bo, pWH + ko + 16);
        CP16(dWL0 + bo, pWL + ko);
        CP16(dWL1 + bo, pWL + ko + 16);
        CP16(dFH + bo, pFH + ko);
        CP16(dFL + bo, pFL + ko);
        CP_COMMIT();
    }

    int acch[2][4][4], accm[2][4][4];
    #pragma unroll
    for (int i = 0; i < 2; i++)
        #pragma unroll
        for (int j = 0; j < 4; j++)
            #pragma unroll
            for (int q = 0; q < 4; q++) { acch[i][j][q] = 0; accm[i][j][q] = 0; }

    const int arow = wm * 32 + (lane & 7) + ((lane >> 3) & 1) * 8;   // + mf*16
    const int ach  = (lane >> 4) & 1;                                // chunk within K=32
    const int brow = wn * 32 + ((lane >> 4) & 1) * 8 + (lane & 7);   // + p*16
    const int bch  = (lane >> 3) & 1;

    #pragma unroll 1
    for (int kt = 0; kt < KD / 64; kt++) {       // 8 stages
        const int buf = kt & 1;
        if (kt < KD / 64 - 1) CP_WAIT1(); else CP_WAIT0();
        __syncthreads();
        const uint32_t sb = smb + buf * BUFB;

        #pragma unroll
        for (int ks = 0; ks < 2; ks++) {         // two K=32 sub-chunks
            const int cA = ks * 2 + ach;
            const int cB = ks * 2 + bch;
            uint32_t bqh[4][2], bql[4][2];
            #pragma unroll
            for (int p = 0; p < 2; p++) {
                uint32_t r[4];
                ldm4(r, sb + sws(256 + brow + p * 16, cB));
                bqh[2 * p][0] = r[0]; bqh[2 * p][1] = r[1];
                bqh[2 * p + 1][0] = r[2]; bqh[2 * p + 1][1] = r[3];
                ldm4(r, sb + sws(320 + brow + p * 16, cB));
                bql[2 * p][0] = r[0]; bql[2 * p][1] = r[1];
                bql[2 * p + 1][0] = r[2]; bql[2 * p + 1][1] = r[3];
            }
            #pragma unroll
            for (int mf = 0; mf < 2; mf++) {
                uint32_t ah[4], al[4];
                ldm4(ah, sb + sws(arow + mf * 16, cA));
                ldm4(al, sb + sws(128 + arow + mf * 16, cA));
                // hh + hl sweep, then lh sweep: the two writes to each
                // accm are >=4 IMMAs apart (breaks RAW chain).
                #pragma unroll
                for (int nf = 0; nf < 4; nf++) {
                    imma(acch[mf][nf], ah, bqh[nf]);   // hh
                    imma(accm[mf][nf], ah, bql[nf]);   // hl
                }
                #pragma unroll
                for (int nf = 0; nf < 4; nf++)
                    imma(accm[mf][nf], al, bqh[nf]);   // lh
            }
        }
        __syncthreads();
        if (kt + 2 < KD / 64) {
            const int ko = (kt + 2) * 64;
            const uint32_t bo = buf * BUFB;
            CP16(dWH0 + bo, pWH + ko);
            CP16(dWH1 + bo, pWH + ko + 16);
            CP16(dWL0 + bo, pWL + ko);
            CP16(dWL1 + bo, pWL + ko + 16);
            CP16(dFH + bo, pFH + ko);
            CP16(dFL + bo, pFL + ko);
            CP_COMMIT();
        }
    }

    // epilogue: scale-combine + bias + relu
    const int g    = lane >> 2;
    const int tig  = lane & 3;
    const int bidx = nt >> 5;                  // 32 tiles per batch
    float sbv[4][2];
    #pragma unroll
    for (int nf = 0; nf < 4; nf++) {
        const int col = nt * 64 + wn * 32 + 2 * tig + nf * 8;
        sbv[nf][0] = g_sf[col];
        sbv[nf][1] = g_sf[col + 1];
    }
    const int nb0 = (nt & 31) * 64 + wn * 32 + 2 * tig;
    #pragma unroll
    for (int mf = 0; mf < 2; mf++) {
        const int o0 = mt * 128 + wm * 32 + mf * 16 + g;
        const float sa0 = g_sa[o0], sa1 = g_sa[o0 + 8];
        const float b0  = bias[o0], b1  = bias[o0 + 8];
        float* r0 = out + ((size_t)(bidx * OUTd + o0) * Nn);
        float* r1 = out + ((size_t)(bidx * OUTd + o0 + 8) * Nn);
        #pragma unroll
        for (int nf = 0; nf < 4; nf++) {
            const int nb = nb0 + nf * 8;
            const float t0 = 16384.f * (float)acch[mf][nf][0] + 128.f * (float)accm[mf][nf][0];
            const float t1 = 16384.f * (float)acch[mf][nf][1] + 128.f * (float)accm[mf][nf][1];
            const float t2 = 16384.f * (float)acch[mf][nf][2] + 128.f * (float)accm[mf][nf][2];
            const float t3 = 16384.f * (float)acch[mf][nf][3] + 128.f * (float)accm[mf][nf][3];
            float2 w0, w1;
            w0.x = fmaxf(fmaf(t0, sa0 * sbv[nf][0], b0), 0.f);
            w0.y = fmaxf(fmaf(t1, sa0 * sbv[nf][1], b0), 0.f);
            w1.x = fmaxf(fmaf(t2, sa1 * sbv[nf][0], b1), 0.f);
            w1.y = fmaxf(fmaf(t3, sa1 * sbv[nf][1], b1), 0.f);
            *(float2*)(r0 + nb) = w0;
            *(float2*)(r1 + nb) = w1;
        }
    }
}

// ============================================================
// launch
// ============================================================
extern "C" void kernel_launch(void* const* d_in, const int* in_sizes, int n_in,
                              void* d_out, int out_size) {
    const float* x    = (const float*)d_in[0];
    const int*   edge = (const int*)d_in[1];
    const float* a_w  = (const float*)d_in[2];
    const float* a_b  = (const float*)d_in[3];
    const float* nn_w = (const float*)d_in[4];
    const float* nn_b = (const float*)d_in[5];
    float*       out  = (float*)d_out;

    k_wq       <<<OUTd, 32>>>(nn_w, edge);
    k_transpose<<<dim3(Nn / 32, Bb), dim3(32, 8)>>>(x, a_w);
    k_agg      <<<BN_TOT / 8, 256>>>(edge, a_b);
    k_gemm_i8  <<<dim3(NT2, MTILES), 256>>>(nn_b, out);
}